// round 9
// baseline (speedup 1.0000x reference)
#include <cuda_runtime.h>
#include <cuda_bf16.h>
#include <math.h>
#include <stdint.h>

// NCE loss: scores(16384x104) = inp(16384x512) @ noise_emb^T via HMMA bf16.
// Grid=128 CTAs x 256 thr, 128 tokens/CTA, 1 CTA/SM.
// Phase-separated: per k-half (256), stage A (bf16) + [noise;target] rows
// (bf16) into smem with burst LDGs, then run a PURE-SMEM ldmatrix+MMA loop
// (zero global loads inside). Target dots are 2 extra MMAs per warp against
// its own 16 target rows (rows 104..231 of the BT tile); diagonal extracted
// from the accumulator layout.

#define E      512
#define NRR    100
#define NP     104          // 13 * 8 noise cols
#define NT     13
#define TPB    256
#define GRID1  128
#define NTOK   16384

#define SM_A     0          // 128 rows * 512B (k-half, swizzled 16B chunks)
#define SM_BT    65536      // 232 rows * 512B (104 noise + 128 target)
#define SM_SC    184320     // 104 floats
#define SM_TC    184800     // 128 floats (bias - logn - csub per token)
#define SM_NID   185312     // 104 ints
#define SM_TGT   185792     // 128 ints
#define SM_RED   186304     // 8 floats
#define SM_FLAG  186368
#define SM_TOTAL 186400

__device__ float        g_partials[GRID1];
__device__ unsigned int g_counter;

__device__ __forceinline__ float softplus_fast(float x) {
    return fmaxf(x, 0.0f) + __logf(1.0f + __expf(-fabsf(x)));
}
__device__ __forceinline__ uint32_t smem_u32(const void* p) {
    uint32_t a;
    asm("{ .reg .u64 t; cvta.to.shared.u64 t, %1; cvt.u32.u64 %0, t; }"
        : "=r"(a) : "l"(p));
    return a;
}
__device__ __forceinline__ uint32_t bf2(float lo, float hi) {
    uint32_t r;
    asm("cvt.rn.bf16x2.f32 %0, %1, %2;" : "=r"(r) : "f"(hi), "f"(lo));
    return r;
}
__device__ __forceinline__ void mma16816(float* d,
        uint32_t a0, uint32_t a1, uint32_t a2, uint32_t a3,
        uint32_t b0, uint32_t b1) {
    asm volatile("mma.sync.aligned.m16n8k16.row.col.f32.bf16.bf16.f32 "
        "{%0,%1,%2,%3}, {%4,%5,%6,%7}, {%8,%9}, {%0,%1,%2,%3};"
        : "+f"(d[0]), "+f"(d[1]), "+f"(d[2]), "+f"(d[3])
        : "r"(a0), "r"(a1), "r"(a2), "r"(a3), "r"(b0), "r"(b1));
}

__global__ void __launch_bounds__(TPB, 1)
nce_hmma(const float* __restrict__ inp,
         const float* __restrict__ emb,
         const float* __restrict__ bias,
         const float* __restrict__ logn,
         const int*   __restrict__ target,
         const int*   __restrict__ noise_idx,
         float csub, float* __restrict__ out)
{
    extern __shared__ char smem[];
    const uint32_t sb = smem_u32(smem);
    const int tid = threadIdx.x, warp = tid >> 5, lane = tid & 31;
    const int gid = lane >> 2, ctg = lane & 3;
    float* sC    = (float*)(smem + SM_SC);
    float* sTC   = (float*)(smem + SM_TC);
    int*   sNid  = (int*)(smem + SM_NID);
    int*   sTgt  = (int*)(smem + SM_TGT);
    float* sRed  = (float*)(smem + SM_RED);
    int*   sFlag = (int*)(smem + SM_FLAG);
    const int tokBase = blockIdx.x * 128;

    // ---- per-token / per-column constants
    if (tid < 128) {
        int tg = target[tokBase + tid];
        sTgt[tid] = tg;
        sTC[tid]  = bias[tg] - logn[tg] - csub;
    }
    if (tid < NP) {
        int nid = (tid < NRR) ? noise_idx[tid] : 0;
        sNid[tid] = nid;
        sC[tid] = (tid < NRR) ? (bias[nid] - logn[nid] - csub) : -INFINITY;
    }
    __syncthreads();

    // ---- accumulators
    float acc[NT][4];
    #pragma unroll
    for (int t = 0; t < NT; ++t)
        #pragma unroll
        for (int r = 0; r < 4; ++r) acc[t][r] = 0.0f;
    float accT[8];
    #pragma unroll
    for (int r = 0; r < 8; ++r) accT[r] = 0.0f;

    // ---- per-lane ldmatrix bases
    // A (row-major m16k16): lanes 0-7 rows 0-7 k0-7 | 8-15 rows 8-15 k0-7 |
    //                       16-23 rows 0-7 k8-15   | 24-31 rows 8-15 k8-15
    const int arow = warp * 16 + (lane & 7) + ((lane >> 3) & 1) * 8;
    const uint32_t aBase = sb + (uint32_t)(SM_A + arow * 512);
    const int am = arow & 7, asel = lane >> 4;
    // T tile (this warp's 16 target rows as B): lanes 0-7 n0-7 k0-7 |
    //   8-15 n0-7 k8-15 | 16-23 n8-15 k0-7 | 24-31 n8-15 k8-15
    const int trow = 104 + warp * 16 + ((lane >> 4) << 3) + (lane & 7);
    const uint32_t tBase = sb + (uint32_t)(SM_BT + trow * 512);
    const int tm = trow & 7, tsel = (lane >> 3) & 1;
    // B slots (R4-proven): 6 x4 (tiles 0..11) + 1 x2 (tile 12)
    int nb[7], m7[7];
    #pragma unroll
    for (int p = 0; p < 6; ++p) {
        int n = (2 * p + (lane >> 4)) * 8 + (lane & 7);
        nb[p] = SM_BT + n * 512; m7[p] = n & 7;
    }
    { int n = 96 + (lane & 7); nb[6] = SM_BT + n * 512; m7[6] = n & 7; }
    const int khB = (lane >> 3) & 1;

    #pragma unroll 1
    for (int h = 0; h < 2; ++h) {
        // ======== stage phase (burst LDG.128, convert, swizzled STS.128) ====
        // A: 128 rows x 32 chunks of 8 bf16
        #pragma unroll
        for (int i = 0; i < 16; ++i) {
            int idx = tid + i * TPB;
            int row = idx >> 5, c = idx & 31;
            const float4* src = (const float4*)(inp + (size_t)(tokBase + row) * E
                                                + h * 256 + c * 8);
            float4 v0 = src[0], v1 = src[1];
            uint4 pk = make_uint4(bf2(v0.x, v0.y), bf2(v0.z, v0.w),
                                  bf2(v1.x, v1.y), bf2(v1.z, v1.w));
            *(uint4*)(smem + SM_A + row * 512 + ((c ^ (row & 7)) << 4)) = pk;
        }
        // BT: 232 rows x 32 chunks (rows 0-99 noise, 100-103 zero, 104-231 target)
        #pragma unroll
        for (int i = 0; i < 29; ++i) {
            int idx = tid + i * TPB;
            if (idx < 232 * 32) {
                int row = idx >> 5, c = idx & 31;
                uint4 pk = make_uint4(0u, 0u, 0u, 0u);
                int srcrow = -1;
                if (row < NRR) srcrow = sNid[row];
                else if (row >= 104) srcrow = sTgt[row - 104];
                if (srcrow >= 0) {
                    const float4* src = (const float4*)(emb + (size_t)srcrow * E
                                                        + h * 256 + c * 8);
                    float4 v0 = src[0], v1 = src[1];
                    pk = make_uint4(bf2(v0.x, v0.y), bf2(v0.z, v0.w),
                                    bf2(v1.x, v1.y), bf2(v1.z, v1.w));
                }
                *(uint4*)(smem + SM_BT + row * 512 + ((c ^ (row & 7)) << 4)) = pk;
            }
        }
        __syncthreads();

        // ======== compute phase: pure smem =================================
        #pragma unroll 4
        for (int ks = 0; ks < 16; ++ks) {
            uint32_t a0, a1, a2, a3;
            {
                int cb = ks * 2 + asel;
                uint32_t addr = aBase + (uint32_t)((cb ^ am) << 4);
                asm volatile("ldmatrix.sync.aligned.m8n8.x4.shared.b16 "
                             "{%0,%1,%2,%3}, [%4];"
                             : "=r"(a0), "=r"(a1), "=r"(a2), "=r"(a3) : "r"(addr));
            }
            {   // target tile: 2 MMAs
                uint32_t t0, t1, t2, t3;
                int cb = ks * 2 + tsel;
                uint32_t addr = tBase + (uint32_t)((cb ^ tm) << 4);
                asm volatile("ldmatrix.sync.aligned.m8n8.x4.shared.b16 "
                             "{%0,%1,%2,%3}, [%4];"
                             : "=r"(t0), "=r"(t1), "=r"(t2), "=r"(t3) : "r"(addr));
                mma16816(accT,     a0, a1, a2, a3, t0, t1);
                mma16816(accT + 4, a0, a1, a2, a3, t2, t3);
            }
            const int cb = ks * 2 + khB;
            #pragma unroll
            for (int p = 0; p < 6; ++p) {
                uint32_t b0, b1, b2, b3;
                uint32_t addr = sb + (uint32_t)(nb[p] + ((cb ^ m7[p]) << 4));
                asm volatile("ldmatrix.sync.aligned.m8n8.x4.shared.b16 "
                             "{%0,%1,%2,%3}, [%4];"
                             : "=r"(b0), "=r"(b1), "=r"(b2), "=r"(b3) : "r"(addr));
                mma16816(acc[2 * p],     a0, a1, a2, a3, b0, b1);
                mma16816(acc[2 * p + 1], a0, a1, a2, a3, b2, b3);
            }
            {
                uint32_t b0, b1;
                uint32_t addr = sb + (uint32_t)(nb[6] + ((cb ^ m7[6]) << 4));
                asm volatile("ldmatrix.sync.aligned.m8n8.x2.shared.b16 "
                             "{%0,%1}, [%2];"
                             : "=r"(b0), "=r"(b1) : "r"(addr));
                mma16816(acc[12], a0, a1, a2, a3, b0, b1);
            }
        }
        __syncthreads();                 // before restaging the shared tiles
    }

    float myLoss = 0.0f;

    // ---- target scores from MMA diagonal:
    // accT[0..3]=tile(tokens 0-7): rows gid/gid+8, cols 2ctg,2ctg+1
    // accT[4..7]=tile(tokens 8-15)
    {
        int t0 = warp * 16 + gid;
        if (gid == 2 * ctg) {            // token gid (row gid, col gid) and
            myLoss += softplus_fast(-(accT[0] + sTC[t0]));        // token gid
            myLoss += softplus_fast(-(accT[6] + sTC[t0 + 8]));    // token gid+8
        } else if (gid == 2 * ctg + 1) {
            myLoss += softplus_fast(-(accT[1] + sTC[t0]));
            myLoss += softplus_fast(-(accT[7] + sTC[t0 + 8]));
        }
    }

    // ---- epilogue: softplus over all 128x104 noise scores
    #pragma unroll
    for (int nt = 0; nt < NT; ++nt) {
        float c0 = sC[nt * 8 + ctg * 2];
        float c1 = sC[nt * 8 + ctg * 2 + 1];
        myLoss += softplus_fast(acc[nt][0] + c0);
        myLoss += softplus_fast(acc[nt][1] + c1);
        myLoss += softplus_fast(acc[nt][2] + c0);
        myLoss += softplus_fast(acc[nt][3] + c1);
    }

    // ---- block reduce
    #pragma unroll
    for (int d = 16; d >= 1; d >>= 1)
        myLoss += __shfl_xor_sync(0xffffffffu, myLoss, d);
    if (lane == 0) sRed[warp] = myLoss;
    __syncthreads();

    // ---- cross-block: last block reduces (single kernel)
    if (tid == 0) {
        float s = 0.f;
        #pragma unroll
        for (int w = 0; w < 8; ++w) s += sRed[w];
        g_partials[blockIdx.x] = s;
        __threadfence();
        unsigned n = atomicAdd(&g_counter, 1u);
        sFlag[0] = (n == GRID1 - 1) ? 1 : 0;
    }
    __syncthreads();
    if (sFlag[0]) {
        float v = (tid < GRID1) ? g_partials[tid] : 0.f;
        #pragma unroll
        for (int d = 16; d >= 1; d >>= 1)
            v += __shfl_xor_sync(0xffffffffu, v, d);
        if (lane == 0) sRed[warp] = v;
        __syncthreads();
        if (tid == 0) {
            float s = 0.f;
            #pragma unroll
            for (int w = 0; w < 8; ++w) s += sRed[w];
            out[0] = s * (1.0f / (float)NTOK);
            g_counter = 0u;                 // reset for next graph replay
        }
    }
}

extern "C" void kernel_launch(void* const* d_in, const int* in_sizes, int n_in,
                              void* d_out, int out_size) {
    (void)in_sizes; (void)n_in; (void)out_size;
    const float* inp       = (const float*)d_in[0];
    const float* emb       = (const float*)d_in[1];
    const float* bias      = (const float*)d_in[2];
    const float* logn      = (const float*)d_in[3];
    const int*   target    = (const int*)d_in[4];
    const int*   noise_idx = (const int*)d_in[5];

    float csub = logf(50257.0f) + logf(100.0f);   // NORM_TERM + LOG_NR

    cudaFuncSetAttribute(nce_hmma, cudaFuncAttributeMaxDynamicSharedMemorySize, SM_TOTAL);
    nce_hmma<<<GRID1, TPB, SM_TOTAL>>>(inp, emb, bias, logn, target, noise_idx,
                                       csub, (float*)d_out);
}